// round 10
// baseline (speedup 1.0000x reference)
#include <cuda_runtime.h>
#include <cuda_bf16.h>
#include <math.h>

// ---------------- Problem constants ----------------
#define TT   4096
#define DD   128
#define HH   512
#define EE   256
#define WN   4
#define H3   1536

// Sequential kernel config
#define NB   64           // persistent blocks
#define NTH  512
#define HB   8            // hidden dims owned per block (NB*HB = 512)

// ---------------- Device scratch ----------------
__device__ float g_pre_x[TT * H3];
__device__ float g_pre_a[TT * HH];
__device__ float g_pre_w[TT * WN * H3];
// Packed partial buffers: [parity][n-group (4 slots)][contributor j] as float4
__device__ float4 g_Pg4[2 * (H3 / 4) * NB];          // h@U partials
__device__ float4 g_Pw4[2 * WN * (H3 / 4) * NB];     // h_s@Uw partials
__device__ float4 g_Pa4[2 * WN * (HH / 4) * NB];     // c_w@Ua partials
__device__ unsigned int g_ctr;
__device__ int g_nact;
__device__ int g_act[TT * WN];
__device__ int g_mask_mode;

// ---------------- Helpers ----------------
__device__ __forceinline__ float sigm(float x) { return 1.0f / (1.0f + __expf(-x)); }
__device__ __forceinline__ float tanh_fast(float x) {
    return 1.0f - 2.0f / (__expf(2.0f * x) + 1.0f);
}
__device__ __forceinline__ bool mask_at(const void* p, int r) {
    int m = g_mask_mode;
    if (m == 1) return ((const int*)p)[r] != 0;
    if (m == 2) return ((const unsigned int*)p)[r] != 0u;
    return ((const unsigned char*)p)[r] != 0;
}
__device__ __forceinline__ void arrive_release(unsigned int* p) {
    asm volatile("red.release.gpu.global.add.u32 [%0], 1;" :: "l"(p) : "memory");
}
__device__ __forceinline__ unsigned int ld_acq(const unsigned int* p) {
    unsigned int v;
    asm volatile("ld.acquire.gpu.global.u32 %0, [%1];" : "=r"(v) : "l"(p) : "memory");
    return v;
}

// ---------------- (0) Init + compact (single block) ----------------
__global__ void k_init_compact(const unsigned int* mask_words, const void* wmask) {
    __shared__ int badI, badF;
    int tid = threadIdx.x;
    if (tid == 0) { badI = 0; badF = 0; g_ctr = 0u; g_nact = 0; }
    __syncthreads();
    for (int i = tid; i < 4096; i += blockDim.x) {
        unsigned int w = mask_words[i];
        if (w != 0u && w != 1u) badI = 1;
        if (w != 0u && w != 0x3F800000u) badF = 1;
    }
    __syncthreads();
    if (tid == 0) g_mask_mode = (badI == 0) ? 1 : ((badF == 0) ? 2 : 0);
    __syncthreads();
    for (int r = tid; r < TT * WN; r += blockDim.x) {
        if (mask_at(wmask, r)) {
            int s = atomicAdd(&g_nact, 1);
            g_act[s] = r;
        }
    }
}

// ---------------- (1) Fused dense GEMMs: pre_x, pre_a ----------------
__global__ void k_gemm_fused(const float* __restrict__ A,
                             const float* __restrict__ W,  const float* __restrict__ b,
                             const float* __restrict__ Wa, const float* __restrict__ ba) {
    __shared__ float As[64][33];
    __shared__ float Bs[32][64];
    int bx = blockIdx.x;
    const float* B; const float* bias; float* C; int N, nt;
    if (bx < H3 / 64) { B = W;  bias = b;  C = g_pre_x; N = H3; nt = bx * 64; }
    else              { B = Wa; bias = ba; C = g_pre_a; N = HH; nt = (bx - H3 / 64) * 64; }
    int mt = blockIdx.y * 64;
    int tid = threadIdx.x;
    int tx = tid % 16, ty = tid / 16;
    float acc[4][4] = {};
    for (int k0 = 0; k0 < DD; k0 += 32) {
        #pragma unroll
        for (int p = 0; p < 8; p++) {
            int row = (tid >> 5) + p * 8, kk = tid & 31;
            As[row][kk] = A[(size_t)(mt + row) * DD + k0 + kk];
        }
        #pragma unroll
        for (int p = 0; p < 8; p++) {
            int kk = (tid >> 6) + p * 4, nn = tid & 63;
            Bs[kk][nn] = B[(size_t)(k0 + kk) * N + nt + nn];
        }
        __syncthreads();
        #pragma unroll
        for (int kk = 0; kk < 32; kk++) {
            float a0 = As[ty * 4 + 0][kk], a1 = As[ty * 4 + 1][kk];
            float a2 = As[ty * 4 + 2][kk], a3 = As[ty * 4 + 3][kk];
            float4 b4 = *(const float4*)&Bs[kk][tx * 4];
            acc[0][0] += a0 * b4.x; acc[0][1] += a0 * b4.y; acc[0][2] += a0 * b4.z; acc[0][3] += a0 * b4.w;
            acc[1][0] += a1 * b4.x; acc[1][1] += a1 * b4.y; acc[1][2] += a1 * b4.z; acc[1][3] += a1 * b4.w;
            acc[2][0] += a2 * b4.x; acc[2][1] += a2 * b4.y; acc[2][2] += a2 * b4.z; acc[2][3] += a2 * b4.w;
            acc[3][0] += a3 * b4.x; acc[3][1] += a3 * b4.y; acc[3][2] += a3 * b4.z; acc[3][3] += a3 * b4.w;
        }
        __syncthreads();
    }
    #pragma unroll
    for (int i = 0; i < 4; i++) {
        int row = mt + ty * 4 + i;
        #pragma unroll
        for (int j = 0; j < 4; j++) {
            int col = nt + tx * 4 + j;
            C[(size_t)row * N + col] = acc[i][j] + bias[col];
        }
    }
}

// ---------------- (2) Gathered GEMM: pre_w for active rows ----------------
__global__ void k_gemm_gather(const float* __restrict__ emb, const int* __restrict__ word_ids,
                              const float* __restrict__ B, const float* __restrict__ bias) {
    int nact = g_nact;
    int mt = blockIdx.y * 64;
    if (mt >= nact) return;
    __shared__ int sR[64];
    __shared__ int sWid[64];
    __shared__ float As[64][33];
    __shared__ float Bs[32][64];
    int tid = threadIdx.x;
    if (tid < 64) {
        int ci = mt + tid;
        int r = (ci < nact) ? g_act[ci] : -1;
        sR[tid] = r;
        sWid[tid] = (r >= 0) ? word_ids[r] : 0;
    }
    __syncthreads();
    int tx = tid % 16, ty = tid / 16;
    int nt = blockIdx.x * 64;
    float acc[4][4] = {};
    for (int k0 = 0; k0 < EE; k0 += 32) {
        #pragma unroll
        for (int p = 0; p < 8; p++) {
            int row = (tid >> 5) + p * 8, kk = tid & 31;
            As[row][kk] = emb[(size_t)sWid[row] * EE + k0 + kk];
        }
        #pragma unroll
        for (int p = 0; p < 8; p++) {
            int kk = (tid >> 6) + p * 4, nn = tid & 63;
            Bs[kk][nn] = B[(size_t)(k0 + kk) * H3 + nt + nn];
        }
        __syncthreads();
        #pragma unroll
        for (int kk = 0; kk < 32; kk++) {
            float a0 = As[ty * 4 + 0][kk], a1 = As[ty * 4 + 1][kk];
            float a2 = As[ty * 4 + 2][kk], a3 = As[ty * 4 + 3][kk];
            float4 b4 = *(const float4*)&Bs[kk][tx * 4];
            acc[0][0] += a0 * b4.x; acc[0][1] += a0 * b4.y; acc[0][2] += a0 * b4.z; acc[0][3] += a0 * b4.w;
            acc[1][0] += a1 * b4.x; acc[1][1] += a1 * b4.y; acc[1][2] += a1 * b4.z; acc[1][3] += a1 * b4.w;
            acc[2][0] += a2 * b4.x; acc[2][1] += a2 * b4.y; acc[2][2] += a2 * b4.z; acc[2][3] += a2 * b4.w;
            acc[3][0] += a3 * b4.x; acc[3][1] += a3 * b4.y; acc[3][2] += a3 * b4.z; acc[3][3] += a3 * b4.w;
        }
        __syncthreads();
    }
    #pragma unroll
    for (int i = 0; i < 4; i++) {
        int r = sR[ty * 4 + i];
        if (r >= 0) {
            #pragma unroll
            for (int j = 0; j < 4; j++) {
                int col = nt + tx * 4 + j;
                g_pre_w[(size_t)r * H3 + col] = acc[i][j] + bias[col];
            }
        }
    }
}

// ---------------- (3) Sequential lattice scan (row-partitioned, packed partials) ----
__global__ void __launch_bounds__(NTH, 1)
k_lattice_seq(const float* __restrict__ h0, const float* __restrict__ c0,
              const int* __restrict__ wstarts, const void* __restrict__ wmask,
              const float* __restrict__ U, const float* __restrict__ Uw,
              const float* __restrict__ Ua, float* __restrict__ out) {
    int tid = threadIdx.x;
    int j = blockIdx.x;              // contributor index
    int hbase = j * HB;

    __shared__ float h_loc[HB], c_loc[HB];
    __shared__ float ig[HB], og[HB], gg[HB];
    __shared__ float cw_loc[WN][HB], cs_loc[WN][HB];
    __shared__ float sHs[WN][HB];            // h_s slices for next-step word partials
    __shared__ float sRed[128];              // reduced slot sums (24 gate + 24*WN word)
    __shared__ float sEA[WN][HB];            // exp(alpha)
    __shared__ float sPreX[2][24], sPreA[2][HB], sPreW[2][WN][24];
    __shared__ int sAct[2][WN], sStart[2][WN], sNact[2];

    // ---------- Prologue ----------
    if (tid < HB) { h_loc[tid] = h0[hbase + tid]; c_loc[tid] = c0[hbase + tid]; }
    if (tid < 24)
        sPreX[0][tid] = g_pre_x[(size_t)(tid / 8) * HH + hbase + (tid % 8)];
    if (tid >= 32 && tid < 32 + HB)
        sPreA[0][tid - 32] = g_pre_a[hbase + (tid - 32)];
    if (tid == 0) {   // metadata for t=0 (mask guarantees nact==0 at t=0)
        int n = 0;
        #pragma unroll
        for (int w = 0; w < WN; w++)
            if (mask_at(wmask, w)) { sAct[0][n] = w; sStart[0][n] = wstarts[w]; n++; }
        sNact[0] = n;
    }
    __syncthreads();
    // contribute h0 @ U partials -> P_g[parity 0]
    if (tid < 384) {
        int n4 = tid * 4;
        float4 acc = make_float4(0.f, 0.f, 0.f, 0.f);
        #pragma unroll
        for (int r = 0; r < HB; r++) {
            float hv = h_loc[r];
            float4 u = __ldg((const float4*)&U[(size_t)(hbase + r) * H3 + n4]);
            acc.x += hv * u.x; acc.y += hv * u.y; acc.z += hv * u.z; acc.w += hv * u.w;
        }
        __stcg(&g_Pg4[(size_t)tid * NB + j], acc);
    }
    __syncthreads();
    unsigned int pno = 1;
    if (tid == 0) {
        arrive_release(&g_ctr);
        while (ld_acq(&g_ctr) < pno * NB) {}
    }
    __syncthreads();

    // ---------- Main loop ----------
    for (int t = 0; t < TT; t++) {
        int p = t & 1, pn = p ^ 1;
        int nact = sNact[p];

        // ===== SEG A: reduce gate + word-gate partials =====
        // groups of 4 slots; 4 subs/group, each sub sums 16 contributors' float4.
        int ngroups = 6 + nact * 6;
        int nthr = (ngroups * 4 + 31) & ~31;
        if (tid < nthr) {
            int g0 = tid >> 2, sub = tid & 3;
            int g = (g0 < ngroups) ? g0 : (ngroups - 1);
            int a = (g < 6) ? -1 : (g - 6) / 6;
            int u = (g < 6) ? g : (g - 6) % 6;      // u in 0..5: m=u>>1, r-quad=u&1
            int m = u >> 1, rq = u & 1;
            int gi = (m * HH + hbase + rq * 4) >> 2;
            const float4* src = (a < 0)
                ? &g_Pg4[((size_t)p * (H3 / 4) + gi) * NB + sub * 16]
                : &g_Pw4[(((size_t)p * WN + sAct[p][a]) * (H3 / 4) + gi) * NB + sub * 16];
            float sx = 0.f, sy = 0.f, sz = 0.f, sw = 0.f;
            #pragma unroll
            for (int i = 0; i < 16; i++) {
                float4 v = __ldcg(src + i);
                sx += v.x; sy += v.y; sz += v.z; sw += v.w;
            }
            sx += __shfl_down_sync(0xffffffffu, sx, 2);
            sy += __shfl_down_sync(0xffffffffu, sy, 2);
            sz += __shfl_down_sync(0xffffffffu, sz, 2);
            sw += __shfl_down_sync(0xffffffffu, sw, 2);
            sx += __shfl_down_sync(0xffffffffu, sx, 1);
            sy += __shfl_down_sync(0xffffffffu, sy, 1);
            sz += __shfl_down_sync(0xffffffffu, sz, 1);
            sw += __shfl_down_sync(0xffffffffu, sw, 1);
            if (sub == 0 && g0 < ngroups) {
                int sbase = (a < 0) ? u * 4 : 24 + a * 24 + u * 4;
                sRed[sbase + 0] = sx; sRed[sbase + 1] = sy;
                sRed[sbase + 2] = sz; sRed[sbase + 3] = sw;
            }
        }
        // c_s loads
        if (tid >= 128 && tid < 128 + nact * HB) {
            int q = tid - 128, a = q / HB, r = q % HB;
            cs_loc[a][r] = __ldcg(out + (size_t)sStart[p][a] * (2 * HH) + HH + hbase + r);
        }
        // metadata for t+1
        if (tid == 480) {
            int m2 = pn, n = 0;
            if (t + 1 < TT) {
                #pragma unroll
                for (int w = 0; w < WN; w++) {
                    int rr = (t + 1) * WN + w;
                    if (mask_at(wmask, rr)) {
                        sAct[m2][n] = w; sStart[m2][n] = wstarts[rr]; n++;
                    }
                }
            }
            sNact[m2] = n;
        }
        __syncthreads();   // S1

        int nact1 = sNact[pn];
        // pointwise gates
        if (tid < HB) {
            int r = tid;
            ig[r] = sigm(sPreX[p][r] + sRed[r]);
            og[r] = sigm(sPreX[p][8 + r] + sRed[8 + r]);
            gg[r] = tanh_fast(sPreX[p][16 + r] + sRed[16 + r]);
        }
        // word cells
        if (tid >= 32 && tid < 32 + nact * HB) {
            int q = tid - 32, a = q / HB, r = q % HB;
            int base = 24 + a * 24;
            float f  = sPreW[p][a][r]      + sRed[base + r];
            float iw = sPreW[p][a][8 + r]  + sRed[base + 8 + r];
            float gw = sPreW[p][a][16 + r] + sRed[base + 16 + r];
            cw_loc[a][r] = sigm(f) * cs_loc[a][r] + sigm(iw) * tanh_fast(gw);
        }
        // h_s slices for next-step words with start<t (already published)
        if (tid >= 64 && tid < 64 + WN * HB) {
            int q = tid - 64, a = q / HB, r = q % HB;
            if (a < nact1 && sStart[pn][a] < t)
                sHs[a][r] = __ldcg(out + (size_t)sStart[pn][a] * (2 * HH) + hbase + r);
        }
        __syncthreads();   // S2

        // alpha partials (this step) + word partials for t+1 (start<t)
        if (tid < 128 && nact > 0) {
            int n4 = tid * 4;
            for (int a = 0; a < nact; a++) {
                float4 acc = make_float4(0.f, 0.f, 0.f, 0.f);
                #pragma unroll
                for (int r = 0; r < HB; r++) {
                    float cv = cw_loc[a][r];
                    float4 u = __ldg((const float4*)&Ua[(size_t)(hbase + r) * HH + n4]);
                    acc.x += cv * u.x; acc.y += cv * u.y; acc.z += cv * u.z; acc.w += cv * u.w;
                }
                __stcg(&g_Pa4[(((size_t)p * WN + sAct[p][a]) * (HH / 4) + tid) * NB + j], acc);
            }
        }
        if (tid >= 128) {
            int gidx = tid - 128;            // 0..383
            int n4 = gidx * 4;
            for (int a = 0; a < nact1; a++) {
                if (sStart[pn][a] < t) {
                    float4 acc = make_float4(0.f, 0.f, 0.f, 0.f);
                    #pragma unroll
                    for (int r = 0; r < HB; r++) {
                        float hv = sHs[a][r];
                        float4 u = __ldg((const float4*)&Uw[(size_t)(hbase + r) * H3 + n4]);
                        acc.x += hv * u.x; acc.y += hv * u.y; acc.z += hv * u.z; acc.w += hv * u.w;
                    }
                    __stcg(&g_Pw4[(((size_t)pn * WN + sAct[pn][a]) * (H3 / 4) + gidx) * NB + j], acc);
                }
            }
        }

        bool prefetched = false;
        if (nact > 0) {
            // ---- barrier B1 (publish c_w@Ua partials) ----
            __syncthreads();
            pno++;
            if (tid == 0) {
                arrive_release(&g_ctr);
                while (ld_acq(&g_ctr) < pno * NB) {}
            } else if (t + 1 < TT) {
                if (tid >= 32 && tid < 56) {
                    int s = tid - 32;
                    sPreX[pn][s] = __ldg(&g_pre_x[(size_t)(t + 1) * H3 + (s / 8) * HH + hbase + (s % 8)]);
                } else if (tid >= 56 && tid < 56 + HB) {
                    sPreA[pn][tid - 56] = __ldg(&g_pre_a[(size_t)(t + 1) * HH + hbase + (tid - 56)]);
                } else if (tid >= 64 && tid < 64 + WN * 24) {
                    int q = tid - 64, a = q / 24, u = q % 24;
                    if (a < nact1)
                        sPreW[pn][a][u] = __ldg(&g_pre_w[(size_t)((t + 1) * WN + sAct[pn][a]) * H3 +
                                                         (u / 8) * HH + hbase + (u % 8)]);
                }
            }
            prefetched = true;
            __syncthreads();

            // ===== SEG B: reduce alpha partials (one warp) =====
            if (tid < 32) {
                int ng = nact * 2;
                int g0 = tid >> 2, sub = tid & 3;
                int g = (g0 < ng) ? g0 : (ng - 1);
                int a = g >> 1, rq = g & 1;
                int gi = (hbase + rq * 4) >> 2;
                const float4* src =
                    &g_Pa4[(((size_t)p * WN + sAct[p][a]) * (HH / 4) + gi) * NB + sub * 16];
                float sx = 0.f, sy = 0.f, sz = 0.f, sw = 0.f;
                #pragma unroll
                for (int i = 0; i < 16; i++) {
                    float4 v = __ldcg(src + i);
                    sx += v.x; sy += v.y; sz += v.z; sw += v.w;
                }
                sx += __shfl_down_sync(0xffffffffu, sx, 2);
                sy += __shfl_down_sync(0xffffffffu, sy, 2);
                sz += __shfl_down_sync(0xffffffffu, sz, 2);
                sw += __shfl_down_sync(0xffffffffu, sw, 2);
                sx += __shfl_down_sync(0xffffffffu, sx, 1);
                sy += __shfl_down_sync(0xffffffffu, sy, 1);
                sz += __shfl_down_sync(0xffffffffu, sz, 1);
                sw += __shfl_down_sync(0xffffffffu, sw, 1);
                if (sub == 0 && g0 < ng) {
                    int rb = rq * 4;
                    sEA[a][rb + 0] = __expf(sigm(sPreA[p][rb + 0] + sx));
                    sEA[a][rb + 1] = __expf(sigm(sPreA[p][rb + 1] + sy));
                    sEA[a][rb + 2] = __expf(sigm(sPreA[p][rb + 2] + sz));
                    sEA[a][rb + 3] = __expf(sigm(sPreA[p][rb + 3] + sw));
                }
            }
            __syncthreads();
        }

        // ---- combine: c1, h1 ----
        if (tid < HB) {
            int r = tid;
            float c1;
            if (nact > 0) {
                float e0 = __expf(ig[r]);
                float num = e0 * gg[r], den = e0;
                for (int a = 0; a < nact; a++) {
                    float ea = sEA[a][r];
                    num += ea * cw_loc[a][r];
                    den += ea;
                }
                c1 = num / den;
            } else {
                c1 = (1.0f - ig[r]) * c_loc[r] + ig[r] * gg[r];
            }
            float h1 = og[r] * tanh_fast(c1);
            __stcg(out + (size_t)t * (2 * HH) + hbase + r, h1);
            __stcg(out + (size_t)t * (2 * HH) + HH + hbase + r, c1);
            h_loc[r] = h1; c_loc[r] = c1;
        }
        if (t == TT - 1) break;
        __syncthreads();   // h_loc visible

        // ---- contributions for t+1: gates (h@U) + len-2 words (start==t) ----
        if (tid < 384) {
            int n4 = tid * 4;
            {
                float4 acc = make_float4(0.f, 0.f, 0.f, 0.f);
                #pragma unroll
                for (int r = 0; r < HB; r++) {
                    float hv = h_loc[r];
                    float4 u = __ldg((const float4*)&U[(size_t)(hbase + r) * H3 + n4]);
                    acc.x += hv * u.x; acc.y += hv * u.y; acc.z += hv * u.z; acc.w += hv * u.w;
                }
                __stcg(&g_Pg4[((size_t)pn * (H3 / 4) + tid) * NB + j], acc);
            }
            for (int a = 0; a < nact1; a++) {
                if (sStart[pn][a] == t) {
                    float4 acc = make_float4(0.f, 0.f, 0.f, 0.f);
                    #pragma unroll
                    for (int r = 0; r < HB; r++) {
                        float hv = h_loc[r];
                        float4 u = __ldg((const float4*)&Uw[(size_t)(hbase + r) * H3 + n4]);
                        acc.x += hv * u.x; acc.y += hv * u.y; acc.z += hv * u.z; acc.w += hv * u.w;
                    }
                    __stcg(&g_Pw4[(((size_t)pn * WN + sAct[pn][a]) * (H3 / 4) + tid) * NB + j], acc);
                }
            }
        }

        // ---- barrier B2 (publish h/c + gate/word partials) ----
        __syncthreads();
        pno++;
        if (tid == 0) {
            arrive_release(&g_ctr);
            while (ld_acq(&g_ctr) < pno * NB) {}
        } else if (!prefetched && t + 1 < TT) {
            if (tid >= 32 && tid < 56) {
                int s = tid - 32;
                sPreX[pn][s] = __ldg(&g_pre_x[(size_t)(t + 1) * H3 + (s / 8) * HH + hbase + (s % 8)]);
            } else if (tid >= 56 && tid < 56 + HB) {
                sPreA[pn][tid - 56] = __ldg(&g_pre_a[(size_t)(t + 1) * HH + hbase + (tid - 56)]);
            } else if (tid >= 64 && tid < 64 + WN * 24) {
                int q = tid - 64, a = q / 24, u = q % 24;
                if (a < nact1)
                    sPreW[pn][a][u] = __ldg(&g_pre_w[(size_t)((t + 1) * WN + sAct[pn][a]) * H3 +
                                                     (u / 8) * HH + hbase + (u % 8)]);
            }
        }
        __syncthreads();
    }
}

// ---------------- Launch ----------------
extern "C" void kernel_launch(void* const* d_in, const int* in_sizes, int n_in,
                              void* d_out, int out_size) {
    const float* x       = (const float*)d_in[0];
    const int*   wids    = (const int*)d_in[1];
    const int*   wstarts = (const int*)d_in[2];
    const void*  wmask   = (const void*)d_in[3];
    const float* h0      = (const float*)d_in[4];
    const float* c0      = (const float*)d_in[5];
    const float* emb     = (const float*)d_in[6];
    const float* W       = (const float*)d_in[7];
    const float* U       = (const float*)d_in[8];
    const float* b       = (const float*)d_in[9];
    const float* Wa      = (const float*)d_in[10];
    const float* Ua      = (const float*)d_in[11];
    const float* ba      = (const float*)d_in[12];
    const float* Ww      = (const float*)d_in[13];
    const float* Uw      = (const float*)d_in[14];
    const float* bw      = (const float*)d_in[15];
    float* out = (float*)d_out;

    k_init_compact<<<1, 512>>>((const unsigned int*)wmask, wmask);            // 0
    k_gemm_fused<<<dim3(H3 / 64 + HH / 64, TT / 64), 256>>>(x, W, b, Wa, ba); // 1
    k_gemm_gather<<<dim3(H3 / 64, (TT * WN) / 64), 256>>>(emb, wids, Ww, bw); // 2
    k_lattice_seq<<<NB, NTH>>>(h0, c0, wstarts, wmask, U, Uw, Ua, out);       // 3 <- ncu slot
}